// round 2
// baseline (speedup 1.0000x reference)
#include <cuda_runtime.h>
#include <cstdint>
#include <math.h>

// ---------------------------------------------------------------------------
// Problem constants
// ---------------------------------------------------------------------------
#define B_  8
#define N_  2048
#define K_  64
#define TU_ 256
#define U_  512
#define BNS 0.9995003746877732f   // np.float32(1/sqrt(1+1e-3))

// ---------------------------------------------------------------------------
// Static scratch (no dynamic allocation allowed)
// ---------------------------------------------------------------------------
__device__ float g_xmax [B_ * TU_];                 // T-net pooled features
__device__ float g_T    [B_ * 9];                   // learned 3x3 transforms
__device__ float g_pts  [B_ * N_ * 3];              // transformed points
__device__ float g_feats[B_ * N_ * 576];            // grouped features / f5 reuse
__device__ float g_bufA [B_ * N_ * 512];
__device__ float g_bufB [B_ * N_ * 512];

// ---------------------------------------------------------------------------
// Kernel 1: T-net 1x1 conv (3->256) + BN + ReLU + global max over N
// grid (B, 8 chunks of 256 rows), block 256 (one thread per unit)
// ---------------------------------------------------------------------------
__global__ void k_tnet_conv_max(const float* __restrict__ points,
                                const float* __restrict__ tw,
                                const float* __restrict__ tb,
                                const float* __restrict__ tg1,
                                const float* __restrict__ tbt1,
                                float* __restrict__ xmax)
{
    int b = blockIdx.x, ch = blockIdx.y;
    int u = threadIdx.x;
    float w0 = tw[u], w1 = tw[TU_ + u], w2 = tw[2 * TU_ + u];
    float bb = tb[u];
    float s  = __fmul_rn(tg1[u], BNS);
    float be = tbt1[u];
    float m = 0.f;
    int n0 = ch * 256;
    for (int n = n0; n < n0 + 256; n++) {
        const float* p = points + ((size_t)b * N_ + n) * 3;
        float v = __fadd_rn(__fadd_rn(__fmul_rn(p[0], w0), __fmul_rn(p[1], w1)),
                            __fmul_rn(p[2], w2));
        v = __fadd_rn(v, bb);
        v = __fadd_rn(__fmul_rn(v, s), be);
        v = fmaxf(v, 0.f);
        m = fmaxf(m, v);
    }
    atomicMax((int*)(xmax + b * TU_ + u), __float_as_int(m));
}

// ---------------------------------------------------------------------------
// Kernel 2: T-net dense stack -> 3x3 transform, one block per batch
// ---------------------------------------------------------------------------
__global__ void k_tnet_dense(const float* __restrict__ xmax,
                             const float* __restrict__ td1w,
                             const float* __restrict__ td1b,
                             const float* __restrict__ tg2,
                             const float* __restrict__ tbt2,
                             const float* __restrict__ td2w,
                             const float* __restrict__ td2b,
                             float* __restrict__ Tm)
{
    __shared__ float xm[TU_];
    __shared__ float h[TU_];
    int b = blockIdx.x;
    int u = threadIdx.x;
    xm[u] = xmax[b * TU_ + u];
    __syncthreads();
    float acc = 0.f;
    for (int i = 0; i < TU_; i++)
        acc = __fadd_rn(acc, __fmul_rn(xm[i], td1w[i * TU_ + u]));
    acc = __fadd_rn(acc, td1b[u]);
    acc = __fadd_rn(__fmul_rn(acc, __fmul_rn(tg2[u], BNS)), tbt2[u]);
    h[u] = fmaxf(acc, 0.f);
    __syncthreads();
    if (u < 9) {
        float a2 = 0.f;
        for (int i = 0; i < TU_; i++)
            a2 = __fadd_rn(a2, __fmul_rn(h[i], td2w[i * 9 + u]));
        Tm[b * 9 + u] = __fadd_rn(a2, td2b[u]);
    }
}

// ---------------------------------------------------------------------------
// Kernel 3: pts = points @ T   (per-point)
// ---------------------------------------------------------------------------
__global__ void k_transform(const float* __restrict__ points,
                            const float* __restrict__ Tm,
                            float* __restrict__ pts)
{
    int idx = blockIdx.x * blockDim.x + threadIdx.x;
    if (idx >= B_ * N_) return;
    int b = idx >> 11;
    const float* T = Tm + b * 9;
    const float* p = points + (size_t)idx * 3;
    float p0 = p[0], p1 = p[1], p2 = p[2];
#pragma unroll
    for (int c = 0; c < 3; c++) {
        float v = __fadd_rn(__fadd_rn(__fmul_rn(p0, T[c]),
                                      __fmul_rn(p1, T[3 + c])),
                            __fmul_rn(p2, T[6 + c]));
        pts[(size_t)idx * 3 + c] = v;
    }
}

// ---------------------------------------------------------------------------
// Kernel 4: per-point multi-radius ball-query top-K + gather -> feats
// One block per (b,n). Exact stable top-64 via full bitonic sort of
// uint64 keys: (score_bits << 32) | ~index  (score >= 0 always).
// ---------------------------------------------------------------------------
__global__ __launch_bounds__(1024)
void k_topk(const float* __restrict__ pts,
            const float* __restrict__ noise,
            float* __restrict__ feats)
{
    __shared__ float spx[N_];
    __shared__ float spy[N_];
    __shared__ float spz[N_];
    __shared__ unsigned long long keys[N_];

    const float RADS[3] = {0.1f, 0.3f, 0.7f};

    int n = blockIdx.x;
    int b = blockIdx.y;
    int tid = threadIdx.x;

    // stage all points of this batch
    for (int e = tid; e < N_; e += 1024) {
        const float* p = pts + ((size_t)b * N_ + e) * 3;
        spx[e] = p[0]; spy[e] = p[1]; spz[e] = p[2];
    }
    __syncthreads();

    float pnx = spx[n], pny = spy[n], pnz = spz[n];
    const float* nrow = noise + ((size_t)b * N_ + n) * N_;
    size_t fbase = ((size_t)b * N_ + n) * 576;

    for (int r = 0; r < 3; r++) {
        float rad = RADS[r];
        // build keys
        for (int e = tid; e < N_; e += 1024) {
            float dx = pnx - spx[e];
            float dy = pny - spy[e];
            float dz = pnz - spz[e];
            float s2 = __fadd_rn(__fadd_rn(__fmul_rn(dx, dx), __fmul_rn(dy, dy)),
                                 __fmul_rn(dz, dz));
            float d = sqrtf(s2);
            float sc = (d <= rad) ? nrow[e] : 0.0f;
            keys[e] = ((unsigned long long)__float_as_uint(sc) << 32)
                    | (unsigned)(~e);
        }
        // bitonic sort, descending (keys are all distinct)
        for (unsigned k = 2; k <= N_; k <<= 1) {
            for (unsigned j = k >> 1; j > 0; j >>= 1) {
                __syncthreads();
                unsigned t = tid;
                unsigned i = 2u * t - (t & (j - 1));
                unsigned p = i + j;
                bool up = (i & k) != 0;          // ascending region
                unsigned long long a = keys[i], c = keys[p];
                if ((a < c) != up) { keys[i] = c; keys[p] = a; }
            }
        }
        __syncthreads();
        // gather top-64 into feats[b, n, k*9 + r*3 + c]
        if (tid < K_) {
            unsigned jdx = ~(unsigned)keys[tid];
            size_t fb = fbase + (size_t)tid * 9 + r * 3;
            feats[fb + 0] = spx[jdx];
            feats[fb + 1] = spy[jdx];
            feats[fb + 2] = spz[jdx];
        }
        __syncthreads();
    }
}

// ---------------------------------------------------------------------------
// Kernel 5: tiled fp32 GEMM, C[M,N] = epi(A[M,K] @ W[K,N] + bias)
// EPI==1: BN + ReLU.  EPI==2: + resid (residual add, C = acc + bias + resid)
// 64x64 block tile, 256 threads, 4x4 micro-tile, K-step 16.
// Requires: M % 64 == 0, K % 16 == 0. N guarded.
// ---------------------------------------------------------------------------
template <int EPI>
__global__ __launch_bounds__(256)
void k_gemm(const float* __restrict__ A, const float* __restrict__ W,
            const float* __restrict__ bias, const float* __restrict__ gamma,
            const float* __restrict__ beta, const float* __restrict__ resid,
            float* __restrict__ C, int M, int N, int Kd)
{
    __shared__ __align__(16) float As[16][64];
    __shared__ __align__(16) float Ws[16][68];

    int tid = threadIdx.x;
    int tx = tid & 15;       // n direction
    int ty = tid >> 4;       // m direction
    int n0 = blockIdx.x * 64;
    int m0 = blockIdx.y * 64;

    float acc[4][4] = {};

    int lk = tid & 15, lm = tid >> 4;     // A-tile load mapping
    int ln = tid & 63, lkw = tid >> 6;    // W-tile load mapping

    for (int k0 = 0; k0 < Kd; k0 += 16) {
#pragma unroll
        for (int r = 0; r < 4; r++) {
            int row = lm + r * 16;
            As[lk][row] = A[(size_t)(m0 + row) * Kd + k0 + lk];
        }
#pragma unroll
        for (int r = 0; r < 4; r++) {
            int kk = lkw + r * 4;
            int col = n0 + ln;
            Ws[kk][ln] = (col < N) ? W[(size_t)(k0 + kk) * N + col] : 0.0f;
        }
        __syncthreads();
#pragma unroll
        for (int kk = 0; kk < 16; kk++) {
            float4 a4 = *(const float4*)&As[kk][ty * 4];
            float4 b4 = *(const float4*)&Ws[kk][tx * 4];
            float av[4] = {a4.x, a4.y, a4.z, a4.w};
            float bv[4] = {b4.x, b4.y, b4.z, b4.w};
#pragma unroll
            for (int i = 0; i < 4; i++)
#pragma unroll
                for (int j = 0; j < 4; j++)
                    acc[i][j] += av[i] * bv[j];
        }
        __syncthreads();
    }

#pragma unroll
    for (int i = 0; i < 4; i++) {
        int row = m0 + ty * 4 + i;
#pragma unroll
        for (int j = 0; j < 4; j++) {
            int col = n0 + tx * 4 + j;
            if (col < N) {
                float v = acc[i][j] + bias[col];
                if (EPI == 1) {
                    v = v * (gamma[col] * BNS) + beta[col];
                    v = fmaxf(v, 0.f);
                } else {
                    v += resid[(size_t)row * N + col];
                }
                C[(size_t)row * N + col] = v;
            }
        }
    }
}

// ---------------------------------------------------------------------------
// Kernel 6: out[b,u] = max_n f[b,n,u]   (f >= 0 after ReLU; out zero-inited)
// grid (B, 8 chunks of 256 rows)
// ---------------------------------------------------------------------------
__global__ void k_maxpool(const float* __restrict__ f, float* __restrict__ out)
{
    int b = blockIdx.x, ch = blockIdx.y;
    int u = threadIdx.x;
    if (u >= 170) return;
    float m = 0.f;
    int n0 = ch * 256;
    for (int n = n0; n < n0 + 256; n++)
        m = fmaxf(m, f[((size_t)b * N_ + n) * 170 + u]);
    atomicMax((int*)(out + b * 170 + u), __float_as_int(m));
}

// ---------------------------------------------------------------------------
// Launch
// ---------------------------------------------------------------------------
extern "C" void kernel_launch(void* const* d_in, const int* in_sizes, int n_in,
                              void* d_out, int out_size)
{
    const float* points = (const float*)d_in[0];
    const float* noise  = (const float*)d_in[1];
    const float* tw     = (const float*)d_in[2];
    const float* tb     = (const float*)d_in[3];
    const float* tg1    = (const float*)d_in[4];
    const float* tbt1   = (const float*)d_in[5];
    const float* td1w   = (const float*)d_in[6];
    const float* td1b   = (const float*)d_in[7];
    const float* tg2    = (const float*)d_in[8];
    const float* tbt2   = (const float*)d_in[9];
    const float* td2w   = (const float*)d_in[10];
    const float* td2b   = (const float*)d_in[11];
    const float* c1w    = (const float*)d_in[12];
    const float* c1b    = (const float*)d_in[13];
    const float* g1     = (const float*)d_in[14];
    const float* be1    = (const float*)d_in[15];
    const float* rw     = (const float*)d_in[16];
    const float* rb     = (const float*)d_in[17];
    const float* b1w    = (const float*)d_in[18];
    const float* b1b    = (const float*)d_in[19];
    const float* b1g    = (const float*)d_in[20];
    const float* b1be   = (const float*)d_in[21];
    const float* b2w    = (const float*)d_in[22];
    const float* b2b    = (const float*)d_in[23];
    const float* b2g    = (const float*)d_in[24];
    const float* b2be   = (const float*)d_in[25];
    const float* b3w    = (const float*)d_in[26];
    const float* b3b    = (const float*)d_in[27];
    const float* b3g    = (const float*)d_in[28];
    const float* b3be   = (const float*)d_in[29];
    float* out = (float*)d_out;

    void *xm, *Tm, *pts, *feats, *bufA, *bufB;
    cudaGetSymbolAddress(&xm,    g_xmax);
    cudaGetSymbolAddress(&Tm,    g_T);
    cudaGetSymbolAddress(&pts,   g_pts);
    cudaGetSymbolAddress(&feats, g_feats);
    cudaGetSymbolAddress(&bufA,  g_bufA);
    cudaGetSymbolAddress(&bufB,  g_bufB);

    // zero atomic-max targets
    cudaMemsetAsync(xm, 0, B_ * TU_ * sizeof(float), 0);
    cudaMemsetAsync(out, 0, B_ * 170 * sizeof(float), 0);

    // T-net
    k_tnet_conv_max<<<dim3(B_, 8), TU_>>>(points, tw, tb, tg1, tbt1, (float*)xm);
    k_tnet_dense<<<B_, TU_>>>((const float*)xm, td1w, td1b, tg2, tbt2, td2w, td2b,
                              (float*)Tm);
    k_transform<<<(B_ * N_ + 255) / 256, 256>>>(points, (const float*)Tm,
                                                (float*)pts);

    // ball query + grouping
    k_topk<<<dim3(N_, B_), 1024>>>((const float*)pts, noise, (float*)feats);

    const int M = B_ * N_;
    // conv1: feats[M,576] @ c1w[576,512], BN+ReLU -> bufA
    k_gemm<1><<<dim3(8, M / 64), 256>>>((const float*)feats, c1w, c1b, g1, be1,
                                        nullptr, (float*)bufA, M, 512, 576);
    // residual: bufA @ rw + rb + bufA -> bufB
    k_gemm<2><<<dim3(8, M / 64), 256>>>((const float*)bufA, rw, rb, nullptr,
                                        nullptr, (const float*)bufA,
                                        (float*)bufB, M, 512, 512);
    // block1: bufB @ b1w, BN+ReLU -> bufA
    k_gemm<1><<<dim3(8, M / 64), 256>>>((const float*)bufB, b1w, b1b, b1g, b1be,
                                        nullptr, (float*)bufA, M, 512, 512);
    // block2: bufA @ b2w, BN+ReLU -> bufB  (N=256)
    k_gemm<1><<<dim3(4, M / 64), 256>>>((const float*)bufA, b2w, b2b, b2g, b2be,
                                        nullptr, (float*)bufB, M, 256, 512);
    // block3: bufB @ b3w, BN+ReLU -> feats (reused as f5)  (N=170)
    k_gemm<1><<<dim3(3, M / 64), 256>>>((const float*)bufB, b3w, b3b, b3g, b3be,
                                        nullptr, (float*)feats, M, 170, 256);

    // global max pool -> out[8,170]
    k_maxpool<<<dim3(B_, 8), 256>>>((const float*)feats, out);
}

// round 4
// speedup vs baseline: 3.2959x; 3.2959x over previous
#include <cuda_runtime.h>
#include <cstdint>
#include <math.h>

// ---------------------------------------------------------------------------
// Problem constants
// ---------------------------------------------------------------------------
#define B_  8
#define N_  2048
#define K_  64
#define TU_ 256
#define U_  512
#define BNS 0.9995003746877732f   // np.float32(1/sqrt(1+1e-3))
#define MAXC 512                  // cap on d<=0.7 candidate superset (mean ~61, 58-sigma margin)

// ---------------------------------------------------------------------------
// Static scratch (no dynamic allocation allowed)
// ---------------------------------------------------------------------------
__device__ float g_xmax [B_ * TU_];                 // T-net pooled features
__device__ float g_T    [B_ * 9];                   // learned 3x3 transforms
__device__ float g_pts  [B_ * N_ * 3];              // transformed points
__device__ float g_feats[B_ * N_ * 576];            // grouped features / f5 reuse
__device__ float g_bufA [B_ * N_ * 512];
__device__ float g_bufB [B_ * N_ * 512];

// ---------------------------------------------------------------------------
// Kernel 1: T-net 1x1 conv (3->256) + BN + ReLU + global max over N
// ---------------------------------------------------------------------------
__global__ void k_tnet_conv_max(const float* __restrict__ points,
                                const float* __restrict__ tw,
                                const float* __restrict__ tb,
                                const float* __restrict__ tg1,
                                const float* __restrict__ tbt1,
                                float* __restrict__ xmax)
{
    int b = blockIdx.x, ch = blockIdx.y;
    int u = threadIdx.x;
    float w0 = tw[u], w1 = tw[TU_ + u], w2 = tw[2 * TU_ + u];
    float bb = tb[u];
    float s  = __fmul_rn(tg1[u], BNS);
    float be = tbt1[u];
    float m = 0.f;
    int n0 = ch * 256;
    for (int n = n0; n < n0 + 256; n++) {
        const float* p = points + ((size_t)b * N_ + n) * 3;
        float v = __fadd_rn(__fadd_rn(__fmul_rn(p[0], w0), __fmul_rn(p[1], w1)),
                            __fmul_rn(p[2], w2));
        v = __fadd_rn(v, bb);
        v = __fadd_rn(__fmul_rn(v, s), be);
        v = fmaxf(v, 0.f);
        m = fmaxf(m, v);
    }
    atomicMax((int*)(xmax + b * TU_ + u), __float_as_int(m));
}

// ---------------------------------------------------------------------------
// Kernel 2: T-net dense stack -> 3x3 transform, one block per batch
// ---------------------------------------------------------------------------
__global__ void k_tnet_dense(const float* __restrict__ xmax,
                             const float* __restrict__ td1w,
                             const float* __restrict__ td1b,
                             const float* __restrict__ tg2,
                             const float* __restrict__ tbt2,
                             const float* __restrict__ td2w,
                             const float* __restrict__ td2b,
                             float* __restrict__ Tm)
{
    __shared__ float xm[TU_];
    __shared__ float h[TU_];
    int b = blockIdx.x;
    int u = threadIdx.x;
    xm[u] = xmax[b * TU_ + u];
    __syncthreads();
    float acc = 0.f;
    for (int i = 0; i < TU_; i++)
        acc = __fadd_rn(acc, __fmul_rn(xm[i], td1w[i * TU_ + u]));
    acc = __fadd_rn(acc, td1b[u]);
    acc = __fadd_rn(__fmul_rn(acc, __fmul_rn(tg2[u], BNS)), tbt2[u]);
    h[u] = fmaxf(acc, 0.f);
    __syncthreads();
    if (u < 9) {
        float a2 = 0.f;
        for (int i = 0; i < TU_; i++)
            a2 = __fadd_rn(a2, __fmul_rn(h[i], td2w[i * 9 + u]));
        Tm[b * 9 + u] = __fadd_rn(a2, td2b[u]);
    }
}

// ---------------------------------------------------------------------------
// Kernel 3: pts = points @ T   (per-point)
// ---------------------------------------------------------------------------
__global__ void k_transform(const float* __restrict__ points,
                            const float* __restrict__ Tm,
                            float* __restrict__ pts)
{
    int idx = blockIdx.x * blockDim.x + threadIdx.x;
    if (idx >= B_ * N_) return;
    int b = idx >> 11;
    const float* T = Tm + b * 9;
    const float* p = points + (size_t)idx * 3;
    float p0 = p[0], p1 = p[1], p2 = p[2];
#pragma unroll
    for (int c = 0; c < 3; c++) {
        float v = __fadd_rn(__fadd_rn(__fmul_rn(p0, T[c]),
                                      __fmul_rn(p1, T[3 + c])),
                            __fadd_rn(__fmul_rn(p2, T[6 + c]), 0.0f));
        pts[(size_t)idx * 3 + c] = v;
    }
}

// ---------------------------------------------------------------------------
// Kernel 4 (rewritten): per-point multi-radius ball-query top-K + gather.
// One block of 256 threads per (b,n).
//
// Observation: score = (d<=rad) ? noise : 0.  Top-64 (stable desc argsort)
// = [candidates with d<=rad && noise>0, sorted desc by (noise, -idx)]
//   followed by fill = smallest indices with score==0 (ascending).
// Candidate counts are tiny (~61 at rad=0.7), so:
//   1. compact d<=0.7 && noise>0 superset once (cap MAXC)
//   2. per radius: filter, bitonic sort only next_pow2(count) elements
//   3. fill via 128-wide ballot prefix scan (fill idx provably < 128)
// Key = (noise_bits<<32) | ~idx  (noise>0 => key > any zero-score key).
// ---------------------------------------------------------------------------
__global__ __launch_bounds__(256)
void k_topk(const float* __restrict__ pts,
            const float* __restrict__ noise,
            float* __restrict__ feats)
{
    __shared__ float spx[N_];
    __shared__ float spy[N_];
    __shared__ float spz[N_];
    __shared__ unsigned long long ckey[MAXC];   // superset keys
    __shared__ float cd[MAXC];                  // superset distances
    __shared__ unsigned long long skey[MAXC];   // per-radius sort buffer
    __shared__ float d128[128];
    __shared__ float n128[128];
    __shared__ int ccount, scount;
    __shared__ int warp_off[8];

    const float RADS[3] = {0.1f, 0.3f, 0.7f};

    int n = blockIdx.x;
    int b = blockIdx.y;
    int tid = threadIdx.x;

    // stage all points of this batch
    for (int e = tid; e < N_; e += 256) {
        const float* p = pts + ((size_t)b * N_ + e) * 3;
        spx[e] = p[0]; spy[e] = p[1]; spz[e] = p[2];
    }
    if (tid == 0) ccount = 0;
    __syncthreads();

    float pnx = spx[n], pny = spy[n], pnz = spz[n];
    const float* nrow = noise + ((size_t)b * N_ + n) * N_;
    size_t fbase = ((size_t)b * N_ + n) * 576;

    // distances + superset compaction (d <= 0.7, noise > 0)
    for (int e = tid; e < N_; e += 256) {
        float dx = pnx - spx[e];
        float dy = pny - spy[e];
        float dz = pnz - spz[e];
        float s2 = __fadd_rn(__fadd_rn(__fmul_rn(dx, dx), __fmul_rn(dy, dy)),
                             __fmul_rn(dz, dz));
        float d = __fsqrt_rn(s2);
        if (e < 128) d128[e] = d;
        if (d <= 0.7f) {
            float nz = nrow[e];
            if (nz > 0.0f) {
                int slot = atomicAdd(&ccount, 1);
                if (slot < MAXC) {
                    ckey[slot] = (((unsigned long long)__float_as_uint(nz)) << 32)
                               | (unsigned)(~e);
                    cd[slot] = d;
                }
            }
        }
    }
    if (tid < 128) n128[tid] = nrow[tid];
    __syncthreads();
    int C7 = min(ccount, MAXC);

    for (int r = 0; r < 3; r++) {
        float rad = RADS[r];

        // per-radius filter from superset
        if (tid == 0) scount = 0;
        __syncthreads();
        for (int i = tid; i < C7; i += 256) {
            if (cd[i] <= rad) {
                int s = atomicAdd(&scount, 1);
                skey[s] = ckey[i];
            }
        }
        __syncthreads();
        int C = scount;

        // pad to power of two with key=0 (sorts to the end)
        int m = 1;
        while (m < C) m <<= 1;
        for (int i = C + tid; i < m; i += 256) skey[i] = 0ULL;
        __syncthreads();

        // bitonic sort descending over m elements (m <= MAXC)
        for (unsigned k = 2; k <= (unsigned)m; k <<= 1) {
            for (unsigned j = k >> 1; j > 0; j >>= 1) {
                for (int t = tid; t < m / 2; t += 256) {
                    unsigned i = 2u * (unsigned)t - ((unsigned)t & (j - 1));
                    unsigned p = i + j;
                    bool up = (i & k) != 0;
                    unsigned long long a = skey[i], c = skey[p];
                    if ((a < c) != up) { skey[i] = c; skey[p] = a; }
                }
                __syncthreads();
            }
        }

        // emit top candidates
        int top = (C < K_) ? C : K_;
        if (tid < top) {
            unsigned jdx = ~(unsigned)skey[tid];
            size_t fb = fbase + (size_t)tid * 9 + r * 3;
            feats[fb + 0] = spx[jdx];
            feats[fb + 1] = spy[jdx];
            feats[fb + 2] = spz[jdx];
        }

        // fill remaining slots with smallest score==0 indices
        int R = K_ - top;
        if (R > 0) {
            int lane = tid & 31, w = tid >> 5;
            bool isz = false;
            if (tid < 128)
                isz = (d128[tid] > rad) || (n128[tid] <= 0.0f);
            unsigned bal = __ballot_sync(0xffffffffu, isz);
            if (tid < 128 && lane == 0) warp_off[w] = __popc(bal);
            __syncthreads();
            if (tid < 128 && isz) {
                int rank = __popc(bal & ((1u << lane) - 1u));
                for (int ww = 0; ww < w; ww++) rank += warp_off[ww];
                if (rank < R) {
                    size_t fb = fbase + (size_t)(top + rank) * 9 + r * 3;
                    feats[fb + 0] = spx[tid];
                    feats[fb + 1] = spy[tid];
                    feats[fb + 2] = spz[tid];
                }
            }
        }
        __syncthreads();
    }
}

// ---------------------------------------------------------------------------
// Kernel 5: tiled fp32 GEMM, C[M,N] = epi(A[M,K] @ W[K,N] + bias)
// EPI==1: BN + ReLU.  EPI==2: + resid
// ---------------------------------------------------------------------------
template <int EPI>
__global__ __launch_bounds__(256)
void k_gemm(const float* __restrict__ A, const float* __restrict__ W,
            const float* __restrict__ bias, const float* __restrict__ gamma,
            const float* __restrict__ beta, const float* __restrict__ resid,
            float* __restrict__ C, int M, int N, int Kd)
{
    __shared__ __align__(16) float As[16][64];
    __shared__ __align__(16) float Ws[16][68];

    int tid = threadIdx.x;
    int tx = tid & 15;       // n direction
    int ty = tid >> 4;       // m direction
    int n0 = blockIdx.x * 64;
    int m0 = blockIdx.y * 64;

    float acc[4][4] = {};

    int lk = tid & 15, lm = tid >> 4;     // A-tile load mapping
    int ln = tid & 63, lkw = tid >> 6;    // W-tile load mapping

    for (int k0 = 0; k0 < Kd; k0 += 16) {
#pragma unroll
        for (int r = 0; r < 4; r++) {
            int row = lm + r * 16;
            As[lk][row] = A[(size_t)(m0 + row) * Kd + k0 + lk];
        }
#pragma unroll
        for (int r = 0; r < 4; r++) {
            int kk = lkw + r * 4;
            int col = n0 + ln;
            Ws[kk][ln] = (col < N) ? W[(size_t)(k0 + kk) * N + col] : 0.0f;
        }
        __syncthreads();
#pragma unroll
        for (int kk = 0; kk < 16; kk++) {
            float4 a4 = *(const float4*)&As[kk][ty * 4];
            float4 b4 = *(const float4*)&Ws[kk][tx * 4];
            float av[4] = {a4.x, a4.y, a4.z, a4.w};
            float bv[4] = {b4.x, b4.y, b4.z, b4.w};
#pragma unroll
            for (int i = 0; i < 4; i++)
#pragma unroll
                for (int j = 0; j < 4; j++)
                    acc[i][j] += av[i] * bv[j];
        }
        __syncthreads();
    }

#pragma unroll
    for (int i = 0; i < 4; i++) {
        int row = m0 + ty * 4 + i;
#pragma unroll
        for (int j = 0; j < 4; j++) {
            int col = n0 + tx * 4 + j;
            if (col < N) {
                float v = acc[i][j] + bias[col];
                if (EPI == 1) {
                    v = v * (gamma[col] * BNS) + beta[col];
                    v = fmaxf(v, 0.f);
                } else {
                    v += resid[(size_t)row * N + col];
                }
                C[(size_t)row * N + col] = v;
            }
        }
    }
}

// ---------------------------------------------------------------------------
// Kernel 6: out[b,u] = max_n f[b,n,u]
// ---------------------------------------------------------------------------
__global__ void k_maxpool(const float* __restrict__ f, float* __restrict__ out)
{
    int b = blockIdx.x, ch = blockIdx.y;
    int u = threadIdx.x;
    if (u >= 170) return;
    float m = 0.f;
    int n0 = ch * 256;
    for (int n = n0; n < n0 + 256; n++)
        m = fmaxf(m, f[((size_t)b * N_ + n) * 170 + u]);
    atomicMax((int*)(out + b * 170 + u), __float_as_int(m));
}

// ---------------------------------------------------------------------------
// Launch
// ---------------------------------------------------------------------------
extern "C" void kernel_launch(void* const* d_in, const int* in_sizes, int n_in,
                              void* d_out, int out_size)
{
    const float* points = (const float*)d_in[0];
    const float* noise  = (const float*)d_in[1];
    const float* tw     = (const float*)d_in[2];
    const float* tb     = (const float*)d_in[3];
    const float* tg1    = (const float*)d_in[4];
    const float* tbt1   = (const float*)d_in[5];
    const float* td1w   = (const float*)d_in[6];
    const float* td1b   = (const float*)d_in[7];
    const float* tg2    = (const float*)d_in[8];
    const float* tbt2   = (const float*)d_in[9];
    const float* td2w   = (const float*)d_in[10];
    const float* td2b   = (const float*)d_in[11];
    const float* c1w    = (const float*)d_in[12];
    const float* c1b    = (const float*)d_in[13];
    const float* g1     = (const float*)d_in[14];
    const float* be1    = (const float*)d_in[15];
    const float* rw     = (const float*)d_in[16];
    const float* rb     = (const float*)d_in[17];
    const float* b1w    = (const float*)d_in[18];
    const float* b1b    = (const float*)d_in[19];
    const float* b1g    = (const float*)d_in[20];
    const float* b1be   = (const float*)d_in[21];
    const float* b2w    = (const float*)d_in[22];
    const float* b2b    = (const float*)d_in[23];
    const float* b2g    = (const float*)d_in[24];
    const float* b2be   = (const float*)d_in[25];
    const float* b3w    = (const float*)d_in[26];
    const float* b3b    = (const float*)d_in[27];
    const float* b3g    = (const float*)d_in[28];
    const float* b3be   = (const float*)d_in[29];
    float* out = (float*)d_out;

    void *xm, *Tm, *pts, *feats, *bufA, *bufB;
    cudaGetSymbolAddress(&xm,    g_xmax);
    cudaGetSymbolAddress(&Tm,    g_T);
    cudaGetSymbolAddress(&pts,   g_pts);
    cudaGetSymbolAddress(&feats, g_feats);
    cudaGetSymbolAddress(&bufA,  g_bufA);
    cudaGetSymbolAddress(&bufB,  g_bufB);

    // zero atomic-max targets
    cudaMemsetAsync(xm, 0, B_ * TU_ * sizeof(float), 0);
    cudaMemsetAsync(out, 0, B_ * 170 * sizeof(float), 0);

    // T-net
    k_tnet_conv_max<<<dim3(B_, 8), TU_>>>(points, tw, tb, tg1, tbt1, (float*)xm);
    k_tnet_dense<<<B_, TU_>>>((const float*)xm, td1w, td1b, tg2, tbt2, td2w, td2b,
                              (float*)Tm);
    k_transform<<<(B_ * N_ + 255) / 256, 256>>>(points, (const float*)Tm,
                                                (float*)pts);

    // ball query + grouping (selection-based, not full sort)
    k_topk<<<dim3(N_, B_), 256>>>((const float*)pts, noise, (float*)feats);

    const int M = B_ * N_;
    // conv1: feats[M,576] @ c1w[576,512], BN+ReLU -> bufA
    k_gemm<1><<<dim3(8, M / 64), 256>>>((const float*)feats, c1w, c1b, g1, be1,
                                        nullptr, (float*)bufA, M, 512, 576);
    // residual: bufA @ rw + rb + bufA -> bufB
    k_gemm<2><<<dim3(8, M / 64), 256>>>((const float*)bufA, rw, rb, nullptr,
                                        nullptr, (const float*)bufA,
                                        (float*)bufB, M, 512, 512);
    // block1: bufB @ b1w, BN+ReLU -> bufA
    k_gemm<1><<<dim3(8, M / 64), 256>>>((const float*)bufB, b1w, b1b, b1g, b1be,
                                        nullptr, (float*)bufA, M, 512, 512);
    // block2: bufA @ b2w, BN+ReLU -> bufB  (N=256)
    k_gemm<1><<<dim3(4, M / 64), 256>>>((const float*)bufA, b2w, b2b, b2g, b2be,
                                        nullptr, (float*)bufB, M, 256, 512);
    // block3: bufB @ b3w, BN+ReLU -> feats (reused as f5)  (N=170)
    k_gemm<1><<<dim3(3, M / 64), 256>>>((const float*)bufB, b3w, b3b, b3g, b3be,
                                        nullptr, (float*)feats, M, 170, 256);

    // global max pool -> out[8,170]
    k_maxpool<<<dim3(B_, 8), 256>>>((const float*)feats, out);
}

// round 5
// speedup vs baseline: 4.6208x; 1.4020x over previous
#include <cuda_runtime.h>
#include <cstdint>
#include <math.h>

// ---------------------------------------------------------------------------
// Problem constants
// ---------------------------------------------------------------------------
#define B_  8
#define N_  2048
#define K_  64
#define TU_ 256
#define U_  512
#define BNS 0.9995003746877732f   // np.float32(1/sqrt(1+1e-3))
#define MAXC 512                  // cap on d<=0.7 candidate superset (mean ~61)

// ---------------------------------------------------------------------------
// Static scratch (no dynamic allocation allowed)
// ---------------------------------------------------------------------------
__device__ __align__(16) float g_xmax [B_ * TU_];
__device__ __align__(16) float g_T    [B_ * 9];
__device__ __align__(16) float g_pts  [B_ * N_ * 3];
__device__ __align__(16) float g_feats[B_ * N_ * 576];
__device__ __align__(16) float g_bufA [B_ * N_ * 512];
__device__ __align__(16) float g_bufB [B_ * N_ * 512];

// ---------------------------------------------------------------------------
// Kernel 1: T-net 1x1 conv (3->256) + BN + ReLU + global max over N
// ---------------------------------------------------------------------------
__global__ void k_tnet_conv_max(const float* __restrict__ points,
                                const float* __restrict__ tw,
                                const float* __restrict__ tb,
                                const float* __restrict__ tg1,
                                const float* __restrict__ tbt1,
                                float* __restrict__ xmax)
{
    int b = blockIdx.x, ch = blockIdx.y;
    int u = threadIdx.x;
    float w0 = tw[u], w1 = tw[TU_ + u], w2 = tw[2 * TU_ + u];
    float bb = tb[u];
    float s  = __fmul_rn(tg1[u], BNS);
    float be = tbt1[u];
    float m = 0.f;
    int n0 = ch * 256;
    for (int n = n0; n < n0 + 256; n++) {
        const float* p = points + ((size_t)b * N_ + n) * 3;
        float v = __fadd_rn(__fadd_rn(__fmul_rn(p[0], w0), __fmul_rn(p[1], w1)),
                            __fmul_rn(p[2], w2));
        v = __fadd_rn(v, bb);
        v = __fadd_rn(__fmul_rn(v, s), be);
        v = fmaxf(v, 0.f);
        m = fmaxf(m, v);
    }
    atomicMax((int*)(xmax + b * TU_ + u), __float_as_int(m));
}

// ---------------------------------------------------------------------------
// Kernel 2: T-net dense stack -> 3x3 transform, one block per batch
// ---------------------------------------------------------------------------
__global__ void k_tnet_dense(const float* __restrict__ xmax,
                             const float* __restrict__ td1w,
                             const float* __restrict__ td1b,
                             const float* __restrict__ tg2,
                             const float* __restrict__ tbt2,
                             const float* __restrict__ td2w,
                             const float* __restrict__ td2b,
                             float* __restrict__ Tm)
{
    __shared__ float xm[TU_];
    __shared__ float h[TU_];
    int b = blockIdx.x;
    int u = threadIdx.x;
    xm[u] = xmax[b * TU_ + u];
    __syncthreads();
    float acc = 0.f;
    for (int i = 0; i < TU_; i++)
        acc = __fadd_rn(acc, __fmul_rn(xm[i], td1w[i * TU_ + u]));
    acc = __fadd_rn(acc, td1b[u]);
    acc = __fadd_rn(__fmul_rn(acc, __fmul_rn(tg2[u], BNS)), tbt2[u]);
    h[u] = fmaxf(acc, 0.f);
    __syncthreads();
    if (u < 9) {
        float a2 = 0.f;
        for (int i = 0; i < TU_; i++)
            a2 = __fadd_rn(a2, __fmul_rn(h[i], td2w[i * 9 + u]));
        Tm[b * 9 + u] = __fadd_rn(a2, td2b[u]);
    }
}

// ---------------------------------------------------------------------------
// Kernel 3: pts = points @ T   (per-point)
// ---------------------------------------------------------------------------
__global__ void k_transform(const float* __restrict__ points,
                            const float* __restrict__ Tm,
                            float* __restrict__ pts)
{
    int idx = blockIdx.x * blockDim.x + threadIdx.x;
    if (idx >= B_ * N_) return;
    int b = idx >> 11;
    const float* T = Tm + b * 9;
    const float* p = points + (size_t)idx * 3;
    float p0 = p[0], p1 = p[1], p2 = p[2];
#pragma unroll
    for (int c = 0; c < 3; c++) {
        float v = __fadd_rn(__fadd_rn(__fmul_rn(p0, T[c]),
                                      __fmul_rn(p1, T[3 + c])),
                            __fmul_rn(p2, T[6 + c]));
        pts[(size_t)idx * 3 + c] = v;
    }
}

// ---------------------------------------------------------------------------
// Kernel 4: multi-radius ball-query top-K. Sort ONCE (d<=0.7 superset, desc
// by key); each radius's top-64 = order-preserving filter of the sorted list.
// Key = (noise_bits<<32) | ~idx. Fill slots = smallest score==0 indices
// (provably within first 128 indices when needed).
// ---------------------------------------------------------------------------
__global__ __launch_bounds__(256)
void k_topk(const float* __restrict__ pts,
            const float* __restrict__ noise,
            float* __restrict__ feats)
{
    __shared__ float sp3[N_ * 3];
    __shared__ unsigned long long ckey[MAXC];
    __shared__ float cd[MAXC];
    __shared__ float d128[128];
    __shared__ float n128[128];
    __shared__ int ccount;
    __shared__ int warp_cnt[8];

    const float RADS[3] = {0.1f, 0.3f, 0.7f};

    int n = blockIdx.x;
    int b = blockIdx.y;
    int tid = threadIdx.x;
    int lane = tid & 31, w = tid >> 5;

    // stage all points of this batch (coalesced)
    for (int e = tid; e < N_ * 3; e += 256)
        sp3[e] = pts[(size_t)b * N_ * 3 + e];
    if (tid == 0) ccount = 0;
    __syncthreads();

    float pnx = sp3[n * 3], pny = sp3[n * 3 + 1], pnz = sp3[n * 3 + 2];
    const float* nrow = noise + ((size_t)b * N_ + n) * N_;
    size_t fbase = ((size_t)b * N_ + n) * 576;

    // distances + superset compaction (d <= 0.7, noise > 0)
    for (int e = tid; e < N_; e += 256) {
        float dx = pnx - sp3[3 * e];
        float dy = pny - sp3[3 * e + 1];
        float dz = pnz - sp3[3 * e + 2];
        float s2 = __fadd_rn(__fadd_rn(__fmul_rn(dx, dx), __fmul_rn(dy, dy)),
                             __fmul_rn(dz, dz));
        float d = __fsqrt_rn(s2);
        if (e < 128) d128[e] = d;
        if (d <= 0.7f) {
            float nz = nrow[e];
            if (nz > 0.0f) {
                int slot = atomicAdd(&ccount, 1);
                if (slot < MAXC) {
                    ckey[slot] = (((unsigned long long)__float_as_uint(nz)) << 32)
                               | (unsigned)(~e);
                    cd[slot] = d;
                }
            }
        }
    }
    if (tid < 128) n128[tid] = nrow[tid];
    __syncthreads();
    int C7 = min(ccount, MAXC);

    // pad to power of two (key 0 sorts to end; keys of real entries > 0)
    int m = 1;
    while (m < C7) m <<= 1;
    for (int i = C7 + tid; i < m; i += 256) { ckey[i] = 0ULL; cd[i] = 1e9f; }
    __syncthreads();

    // single descending bitonic sort of (ckey, cd) pairs
    if (m <= 64) {
        // single-warp path: no block barriers
        if (w == 0) {
            for (unsigned k = 2; k <= (unsigned)m; k <<= 1) {
                for (unsigned j = k >> 1; j > 0; j >>= 1) {
                    unsigned t = (unsigned)lane;
                    if ((int)t < m / 2) {
                        unsigned i = 2u * t - (t & (j - 1));
                        unsigned p = i + j;
                        bool up = (i & k) != 0;
                        unsigned long long a = ckey[i], c = ckey[p];
                        if ((a < c) != up) {
                            ckey[i] = c; ckey[p] = a;
                            float da = cd[i], dc = cd[p];
                            cd[i] = dc; cd[p] = da;
                        }
                    }
                    __syncwarp();
                }
            }
        }
        __syncthreads();
    } else {
        for (unsigned k = 2; k <= (unsigned)m; k <<= 1) {
            for (unsigned j = k >> 1; j > 0; j >>= 1) {
                for (int t = tid; t < m / 2; t += 256) {
                    unsigned i = 2u * (unsigned)t - ((unsigned)t & (j - 1));
                    unsigned p = i + j;
                    bool up = (i & k) != 0;
                    unsigned long long a = ckey[i], c = ckey[p];
                    if ((a < c) != up) {
                        ckey[i] = c; ckey[p] = a;
                        float da = cd[i], dc = cd[p];
                        cd[i] = dc; cd[p] = da;
                    }
                }
                __syncthreads();
            }
        }
    }

    // per-radius: filter sorted list (order preserved), then fill
    for (int r = 0; r < 3; r++) {
        float rad = RADS[r];
        int base = 0;
        for (int c0 = 0; c0 < C7; c0 += 256) {
            int i = c0 + tid;
            bool f = (i < C7) && (cd[i] <= rad);
            unsigned bal = __ballot_sync(0xffffffffu, f);
            if (lane == 0) warp_cnt[w] = __popc(bal);
            __syncthreads();
            int rank = base + __popc(bal & ((1u << lane) - 1u));
            for (int ww = 0; ww < w; ww++) rank += warp_cnt[ww];
            if (f && rank < K_) {
                unsigned jdx = ~(unsigned)ckey[i];
                size_t fb = fbase + (size_t)rank * 9 + r * 3;
                feats[fb + 0] = sp3[3 * jdx];
                feats[fb + 1] = sp3[3 * jdx + 1];
                feats[fb + 2] = sp3[3 * jdx + 2];
            }
            int tot = 0;
            for (int ww = 0; ww < 8; ww++) tot += warp_cnt[ww];
            base += tot;
            __syncthreads();
        }
        int top = (base < K_) ? base : K_;
        int R = K_ - top;
        if (R > 0) {
            bool isz = (tid < 128) &&
                       ((d128[tid] > rad) || (n128[tid] <= 0.0f));
            unsigned bal = __ballot_sync(0xffffffffu, isz);
            if (tid < 128 && lane == 0) warp_cnt[w] = __popc(bal);
            __syncthreads();
            if (isz) {
                int rank = __popc(bal & ((1u << lane) - 1u));
                for (int ww = 0; ww < w; ww++) rank += warp_cnt[ww];
                if (rank < R) {
                    size_t fb = fbase + (size_t)(top + rank) * 9 + r * 3;
                    feats[fb + 0] = sp3[3 * tid];
                    feats[fb + 1] = sp3[3 * tid + 1];
                    feats[fb + 2] = sp3[3 * tid + 2];
                }
            }
            __syncthreads();
        }
    }
}

// ---------------------------------------------------------------------------
// Kernel 5: 128x128x8 double-buffered fp32 GEMM, 256 threads, 8x8 micro-tile.
// EPI==1: BN+ReLU store.  EPI==2: +bias+resid store.
// EPI==3: BN+ReLU then per-batch atomicMax into C[8,170] (fused max-pool).
// Requires M % 128 == 0, Kd % 8 == 0. N guarded (scalar B loads if N%4 != 0).
// ---------------------------------------------------------------------------
template <int EPI>
__global__ __launch_bounds__(256, 2)
void k_gemm128(const float* __restrict__ A, const float* __restrict__ W,
               const float* __restrict__ bias, const float* __restrict__ gamma,
               const float* __restrict__ beta, const float* __restrict__ resid,
               float* __restrict__ C, int M, int N, int Kd)
{
    __shared__ __align__(16) float As[2][8][132];
    __shared__ __align__(16) float Bs[2][8][128];

    const int tid = threadIdx.x;
    const int tx = tid & 15;          // n micro direction
    const int ty = tid >> 4;          // m micro direction
    const int m0 = blockIdx.y * 128;
    const int n0 = blockIdx.x * 128;

    // A tile load mapping: one float4 per thread
    const int arow = tid >> 1;
    const int akh  = (tid & 1) * 4;
    // B tile load mapping: one float4 per thread
    const int bkk = tid >> 5;
    const int bn  = (tid & 31) * 4;
    const bool nvec = ((N & 3) == 0);

    float4 areg, breg;
    float acc[8][8];
#pragma unroll
    for (int i = 0; i < 8; i++)
#pragma unroll
        for (int j = 0; j < 8; j++) acc[i][j] = 0.f;

    // ---- prologue: load k-tile 0 ----
    areg = *(const float4*)&A[(size_t)(m0 + arow) * Kd + akh];
    {
        const float* wp = &W[(size_t)bkk * N];
        int col = n0 + bn;
        if (nvec && col + 3 < N) breg = *(const float4*)&wp[col];
        else {
            breg.x = (col + 0 < N) ? wp[col + 0] : 0.f;
            breg.y = (col + 1 < N) ? wp[col + 1] : 0.f;
            breg.z = (col + 2 < N) ? wp[col + 2] : 0.f;
            breg.w = (col + 3 < N) ? wp[col + 3] : 0.f;
        }
    }
    int cur = 0;
    As[0][akh + 0][arow] = areg.x;
    As[0][akh + 1][arow] = areg.y;
    As[0][akh + 2][arow] = areg.z;
    As[0][akh + 3][arow] = areg.w;
    *(float4*)&Bs[0][bkk][bn] = breg;
    __syncthreads();

    for (int k0 = 0; k0 < Kd; k0 += 8) {
        bool has_next = (k0 + 8 < Kd);
        if (has_next) {
            areg = *(const float4*)&A[(size_t)(m0 + arow) * Kd + k0 + 8 + akh];
            const float* wp = &W[(size_t)(k0 + 8 + bkk) * N];
            int col = n0 + bn;
            if (nvec && col + 3 < N) breg = *(const float4*)&wp[col];
            else {
                breg.x = (col + 0 < N) ? wp[col + 0] : 0.f;
                breg.y = (col + 1 < N) ? wp[col + 1] : 0.f;
                breg.z = (col + 2 < N) ? wp[col + 2] : 0.f;
                breg.w = (col + 3 < N) ? wp[col + 3] : 0.f;
            }
        }
#pragma unroll
        for (int kk = 0; kk < 8; kk++) {
            float4 a0 = *(const float4*)&As[cur][kk][ty * 4];
            float4 a1 = *(const float4*)&As[cur][kk][64 + ty * 4];
            float4 b0 = *(const float4*)&Bs[cur][kk][tx * 4];
            float4 b1 = *(const float4*)&Bs[cur][kk][64 + tx * 4];
            float av[8] = {a0.x, a0.y, a0.z, a0.w, a1.x, a1.y, a1.z, a1.w};
            float bv[8] = {b0.x, b0.y, b0.z, b0.w, b1.x, b1.y, b1.z, b1.w};
#pragma unroll
            for (int i = 0; i < 8; i++)
#pragma unroll
                for (int j = 0; j < 8; j++)
                    acc[i][j] += av[i] * bv[j];
        }
        if (has_next) {
            int nxt = cur ^ 1;
            As[nxt][akh + 0][arow] = areg.x;
            As[nxt][akh + 1][arow] = areg.y;
            As[nxt][akh + 2][arow] = areg.z;
            As[nxt][akh + 3][arow] = areg.w;
            *(float4*)&Bs[nxt][bkk][bn] = breg;
            __syncthreads();
            cur = nxt;
        }
    }

    // ---- epilogue ----
    if (EPI == 3) {
        // BN+ReLU, reduce over this thread's 8 rows, atomicMax per column.
        int bidx = m0 >> 11;   // all 128 rows of this block share a batch
#pragma unroll
        for (int jh = 0; jh < 2; jh++)
#pragma unroll
            for (int j = 0; j < 4; j++) {
                int col = n0 + jh * 64 + tx * 4 + j;
                if (col < N) {
                    float gs = gamma[col] * BNS;
                    float bt = beta[col];
                    float bs = bias[col];
                    float mv = 0.f;
#pragma unroll
                    for (int ii = 0; ii < 8; ii++) {
                        float v = fmaxf((acc[ii][jh * 4 + j] + bs) * gs + bt, 0.f);
                        mv = fmaxf(mv, v);
                    }
                    atomicMax((int*)&C[(size_t)bidx * 170 + col],
                              __float_as_int(mv));
                }
            }
    } else {
#pragma unroll
        for (int ih = 0; ih < 2; ih++)
#pragma unroll
            for (int i = 0; i < 4; i++) {
                int row = m0 + ih * 64 + ty * 4 + i;
#pragma unroll
                for (int jh = 0; jh < 2; jh++)
#pragma unroll
                    for (int j = 0; j < 4; j++) {
                        int col = n0 + jh * 64 + tx * 4 + j;
                        if (col < N) {
                            float v = acc[ih * 4 + i][jh * 4 + j] + bias[col];
                            if (EPI == 1) {
                                v = v * (gamma[col] * BNS) + beta[col];
                                v = fmaxf(v, 0.f);
                            } else {
                                v += resid[(size_t)row * N + col];
                            }
                            C[(size_t)row * N + col] = v;
                        }
                    }
            }
    }
}

// ---------------------------------------------------------------------------
// Launch
// ---------------------------------------------------------------------------
extern "C" void kernel_launch(void* const* d_in, const int* in_sizes, int n_in,
                              void* d_out, int out_size)
{
    const float* points = (const float*)d_in[0];
    const float* noise  = (const float*)d_in[1];
    const float* tw     = (const float*)d_in[2];
    const float* tb     = (const float*)d_in[3];
    const float* tg1    = (const float*)d_in[4];
    const float* tbt1   = (const float*)d_in[5];
    const float* td1w   = (const float*)d_in[6];
    const float* td1b   = (const float*)d_in[7];
    const float* tg2    = (const float*)d_in[8];
    const float* tbt2   = (const float*)d_in[9];
    const float* td2w   = (const float*)d_in[10];
    const float* td2b   = (const float*)d_in[11];
    const float* c1w    = (const float*)d_in[12];
    const float* c1b    = (const float*)d_in[13];
    const float* g1     = (const float*)d_in[14];
    const float* be1    = (const float*)d_in[15];
    const float* rw     = (const float*)d_in[16];
    const float* rb     = (const float*)d_in[17];
    const float* b1w    = (const float*)d_in[18];
    const float* b1b    = (const float*)d_in[19];
    const float* b1g    = (const float*)d_in[20];
    const float* b1be   = (const float*)d_in[21];
    const float* b2w    = (const float*)d_in[22];
    const float* b2b    = (const float*)d_in[23];
    const float* b2g    = (const float*)d_in[24];
    const float* b2be   = (const float*)d_in[25];
    const float* b3w    = (const float*)d_in[26];
    const float* b3b    = (const float*)d_in[27];
    const float* b3g    = (const float*)d_in[28];
    const float* b3be   = (const float*)d_in[29];
    float* out = (float*)d_out;

    void *xm, *Tm, *pts, *feats, *bufA, *bufB;
    cudaGetSymbolAddress(&xm,    g_xmax);
    cudaGetSymbolAddress(&Tm,    g_T);
    cudaGetSymbolAddress(&pts,   g_pts);
    cudaGetSymbolAddress(&feats, g_feats);
    cudaGetSymbolAddress(&bufA,  g_bufA);
    cudaGetSymbolAddress(&bufB,  g_bufB);

    // zero atomic-max targets
    cudaMemsetAsync(xm, 0, B_ * TU_ * sizeof(float), 0);
    cudaMemsetAsync(out, 0, B_ * 170 * sizeof(float), 0);

    // T-net
    k_tnet_conv_max<<<dim3(B_, 8), TU_>>>(points, tw, tb, tg1, tbt1, (float*)xm);
    k_tnet_dense<<<B_, TU_>>>((const float*)xm, td1w, td1b, tg2, tbt2, td2w, td2b,
                              (float*)Tm);
    k_transform<<<(B_ * N_ + 255) / 256, 256>>>(points, (const float*)Tm,
                                                (float*)pts);

    // ball query + grouping
    k_topk<<<dim3(N_, B_), 256>>>((const float*)pts, noise, (float*)feats);

    const int M = B_ * N_;
    // conv1: feats[M,576] @ c1w[576,512], BN+ReLU -> bufA
    k_gemm128<1><<<dim3(4, M / 128), 256>>>((const float*)feats, c1w, c1b, g1,
                                            be1, nullptr, (float*)bufA,
                                            M, 512, 576);
    // residual: bufA @ rw + rb + bufA -> bufB
    k_gemm128<2><<<dim3(4, M / 128), 256>>>((const float*)bufA, rw, rb, nullptr,
                                            nullptr, (const float*)bufA,
                                            (float*)bufB, M, 512, 512);
    // block1: bufB @ b1w, BN+ReLU -> bufA
    k_gemm128<1><<<dim3(4, M / 128), 256>>>((const float*)bufB, b1w, b1b, b1g,
                                            b1be, nullptr, (float*)bufA,
                                            M, 512, 512);
    // block2: bufA @ b2w, BN+ReLU -> bufB  (N=256)
    k_gemm128<1><<<dim3(2, M / 128), 256>>>((const float*)bufA, b2w, b2b, b2g,
                                            b2be, nullptr, (float*)bufB,
                                            M, 256, 512);
    // block3 + fused max-pool: bufB @ b3w, BN+ReLU, atomicMax -> out[8,170]
    k_gemm128<3><<<dim3(2, M / 128), 256>>>((const float*)bufB, b3w, b3b, b3g,
                                            b3be, nullptr, out,
                                            M, 170, 256);
}